// round 7
// baseline (speedup 1.0000x reference)
#include <cuda_runtime.h>
#include <cuda_bf16.h>
#include <math.h>
#include <stdint.h>

// CTRNN B=8192, N=512, K=512, 6 unfolds + 1 precompute GEMM.
// bf16 split-precision (hi/lo) GEMM on mma.sync.m16n8k16.
// R7: barrier-free mainloop. B (weights, hi+lo) resident in smem for full K
//     (128 KB, loaded once, one syncthreads). A is warp-private: each warp
//     owns 32 rows with its own 3-stage cp.async ring -> wait_group+syncwarp
//     only, zero CTA barriers in the mainloop. 1 CTA/SM, 255-reg budget.

#define BB 8192
#define NN 512
#define KK 512

// ---- scratch (device globals; no allocs allowed) ----
__device__ __nv_bfloat16 g_in_hi[BB * KK];
__device__ __nv_bfloat16 g_in_lo[BB * KK];
__device__ __nv_bfloat16 g_s_hi[2][BB * NN];
__device__ __nv_bfloat16 g_s_lo[2][BB * NN];
__device__ float         g_P[BB * NN];
__device__ __nv_bfloat16 g_WtIn_hi[NN * KK];
__device__ __nv_bfloat16 g_WtIn_lo[NN * KK];
__device__ __nv_bfloat16 g_WtRec_hi[NN * KK];
__device__ __nv_bfloat16 g_WtRec_lo[NN * KK];

// ---- helpers ----
__device__ __forceinline__ uint32_t smem_u32(const void* p) {
    uint32_t a;
    asm("{ .reg .u64 t; cvta.to.shared.u64 t, %1; cvt.u32.u64 %0, t; }" : "=r"(a) : "l"(p));
    return a;
}
__device__ __forceinline__ void cp_async16(uint32_t dst, const void* src) {
    asm volatile("cp.async.cg.shared.global [%0], [%1], 16;" :: "r"(dst), "l"(src));
}
#define CP_COMMIT() asm volatile("cp.async.commit_group;" ::: "memory")
#define CP_WAIT2()  asm volatile("cp.async.wait_group 2;" ::: "memory")
#define CP_WAIT1()  asm volatile("cp.async.wait_group 1;" ::: "memory")
#define CP_WAIT0()  asm volatile("cp.async.wait_group 0;" ::: "memory")

__device__ __forceinline__ void ldm4(uint32_t* r, uint32_t addr) {
    asm volatile("ldmatrix.sync.aligned.m8n8.x4.shared.b16 {%0,%1,%2,%3}, [%4];"
                 : "=r"(r[0]), "=r"(r[1]), "=r"(r[2]), "=r"(r[3]) : "r"(addr));
}
__device__ __forceinline__ void mma16816(float* d, const uint32_t* a, uint32_t b0, uint32_t b1) {
    asm volatile(
        "mma.sync.aligned.m16n8k16.row.col.f32.bf16.bf16.f32 "
        "{%0,%1,%2,%3}, {%4,%5,%6,%7}, {%8,%9}, {%0,%1,%2,%3};"
        : "+f"(d[0]), "+f"(d[1]), "+f"(d[2]), "+f"(d[3])
        : "r"(a[0]), "r"(a[1]), "r"(a[2]), "r"(a[3]), "r"(b0), "r"(b1));
}

// ---- geometry ----
#define TM 256                 // CTA rows (32 per warp, 8 warps)
#define TN 64                  // CTA cols (all warps use all 64)
#define TKC 32                 // A chunk in K
#define NCHUNK (KK / TKC)      // 16
#define NSTAGE 3
// SMEM layout (1024-aligned base):
//  [0, 65536)        B hi: 64 rows(cols) x 1024B (K=512 bf16), XOR-swizzled
//  [65536, 131072)   B lo: same
//  [131072, 229376)  per-warp A rings: warp w at +w*12288; 3 stages x 4096
//                    stage: Ahi 32x64B (2048) then Alo (2048); XOR-swizzled
#define OFF_BLO 65536
#define OFF_ARING 131072
#define ASTAGE_SZ 4096
#define AWARP_SZ (NSTAGE * ASTAGE_SZ)
#define DSMEM (1024 + 131072 + 8 * AWARP_SZ)   // 230400 <= 232448

__global__ __launch_bounds__(256, 1)
void ctrnn_hmma(const __nv_bfloat16* __restrict__ Ahi,
                const __nv_bfloat16* __restrict__ Alo,
                const __nv_bfloat16* __restrict__ Bhi,   // Wt [N][K]
                const __nv_bfloat16* __restrict__ Blo,
                const float* __restrict__ P,             // mode1 in
                const float* __restrict__ bias,          // mode0 in
                float* __restrict__ Pout,                // mode0 out
                __nv_bfloat16* __restrict__ NShi,        // mode1 outs
                __nv_bfloat16* __restrict__ NSlo,
                float* __restrict__ OutF,
                float* __restrict__ OutF2,
                int mode)
{
    extern __shared__ char dsm_raw[];
    const uint32_t dsm = (smem_u32(dsm_raw) + 1023u) & ~1023u;

    const int tid = threadIdx.x;
    const int w = tid >> 5;
    const int lane = tid & 31;
    const int br = blockIdx.y * TM;
    const int bc = blockIdx.x * TN;
    const int arow0 = br + w * 32;          // warp-private A rows

    // ---- B fill: 128 KB once (hi then lo regions), swizzled 1024B rows ----
    // 8192 16B-chunks; 32 per thread.
    #pragma unroll
    for (int j = 0; j < 16; j++) {
        int idx = j * 256 + tid;            // 0..4095 within hi region
        int r = idx >> 6, q = idx & 63;     // r: B col (0..63), q: 16B quad
        uint32_t d = dsm + (uint32_t)(r * 1024 + ((q ^ (r & 7)) * 16));
        cp_async16(d,            Bhi + (size_t)(bc + r) * 512 + q * 8);
        cp_async16(d + OFF_BLO,  Blo + (size_t)(bc + r) * 512 + q * 8);
    }
    CP_COMMIT();                            // group: B

    // ---- A ring prologue: chunks 0 and 1 into stages 0,1 (warp-private) ----
    const uint32_t aring = dsm + OFF_ARING + w * AWARP_SZ;
    #pragma unroll
    for (int s = 0; s < 2; s++) {
        uint32_t sb = aring + s * ASTAGE_SZ;
        int kc = s * TKC;
        #pragma unroll
        for (int j = 0; j < 4; j++) {
            int idx = j * 32 + lane;        // 0..127
            int r = idx >> 2, q = idx & 3;
            uint32_t d = sb + (uint32_t)(r * 64 + ((q ^ ((r >> 1) & 3)) * 16));
            cp_async16(d,        Ahi + (size_t)(arow0 + r) * 512 + kc + q * 8);
            cp_async16(d + 2048, Alo + (size_t)(arow0 + r) * 512 + kc + q * 8);
        }
        CP_COMMIT();                        // groups: A c0, A c1
    }

    // wait for B (allow the two A groups to stay in flight), then CTA sync.
    CP_WAIT2();
    __syncthreads();                        // the ONLY CTA barrier pre-epilogue

    // ---- per-lane ldmatrix bases ----
    // A (64B rows, 32 rows/stage): row = mi*16 + (lane&15), quad c = lane>>4
    uint32_t abase[2];
    {
        int arl = lane & 15, c = lane >> 4;
        #pragma unroll
        for (int mi = 0; mi < 2; mi++) {
            int row = mi * 16 + arl;
            abase[mi] = (uint32_t)(row * 64 + ((c ^ ((row >> 1) & 3)) * 16));
        }
    }
    // B (1024B rows): row = p*16 + (lane>>4)*8 + (lane&7), quad c = (lane>>3)&1
    uint32_t bbase[4];
    {
        int brow = (lane >> 4) * 8 + (lane & 7), c = (lane >> 3) & 1;
        #pragma unroll
        for (int p = 0; p < 4; p++) {
            int row = p * 16 + brow;
            bbase[p] = dsm + (uint32_t)(row * 1024 + ((c ^ (row & 7)) * 16));
        }
    }

    float acc[2][8][4];
    #pragma unroll
    for (int mi = 0; mi < 2; mi++)
        #pragma unroll
        for (int ni = 0; ni < 8; ni++)
            #pragma unroll
            for (int q = 0; q < 4; q++) acc[mi][ni][q] = 0.0f;

    // ---- barrier-free mainloop ----
    for (int i = 0; i < NCHUNK; i++) {
        if (i == NCHUNK - 1) { CP_WAIT0(); } else { CP_WAIT1(); }
        __syncwarp();                        // make other lanes' cp.async visible
        if (i + 2 < NCHUNK) {
            uint32_t sb = aring + ((i + 2) % NSTAGE) * ASTAGE_SZ;
            int kc = (i + 2) * TKC;
            #pragma unroll
            for (int j = 0; j < 4; j++) {
                int idx = j * 32 + lane;
                int r = idx >> 2, q = idx & 3;
                uint32_t d = sb + (uint32_t)(r * 64 + ((q ^ ((r >> 1) & 3)) * 16));
                cp_async16(d,        Ahi + (size_t)(arow0 + r) * 512 + kc + q * 8);
                cp_async16(d + 2048, Alo + (size_t)(arow0 + r) * 512 + kc + q * 8);
            }
            CP_COMMIT();
        }

        const uint32_t sb = aring + (i % NSTAGE) * ASTAGE_SZ;
        #pragma unroll
        for (int h = 0; h < 2; h++) {
            const uint32_t akx = (uint32_t)(h * 32);          // A k16 select
            const uint32_t bkx = (uint32_t)((i * 2 + h) * 32); // B k16 select

            // phase 1: Ah x Bh (ah, bh stay live)
            uint32_t ah[2][4], bh[4][4];
            #pragma unroll
            for (int mi = 0; mi < 2; mi++)
                ldm4(ah[mi], (sb + abase[mi]) ^ akx);
            #pragma unroll
            for (int p = 0; p < 4; p++)
                ldm4(bh[p], bbase[p] ^ bkx);
            #pragma unroll
            for (int mi = 0; mi < 2; mi++)
                #pragma unroll
                for (int ni = 0; ni < 8; ni++) {
                    const uint32_t* B = bh[ni >> 1];
                    const int o = (ni & 1) * 2;
                    mma16816(acc[mi][ni], ah[mi], B[o], B[o + 1]);
                }

            // phase 2: Ah x Bl (bl transient)
            {
                uint32_t bl[4][4];
                #pragma unroll
                for (int p = 0; p < 4; p++)
                    ldm4(bl[p], (bbase[p] + OFF_BLO) ^ bkx);
                #pragma unroll
                for (int mi = 0; mi < 2; mi++)
                    #pragma unroll
                    for (int ni = 0; ni < 8; ni++) {
                        const uint32_t* B = bl[ni >> 1];
                        const int o = (ni & 1) * 2;
                        mma16816(acc[mi][ni], ah[mi], B[o], B[o + 1]);
                    }
            }

            // phase 3: Al x Bh (al transient)
            {
                uint32_t al[2][4];
                #pragma unroll
                for (int mi = 0; mi < 2; mi++)
                    ldm4(al[mi], (sb + 2048 + abase[mi]) ^ akx);
                #pragma unroll
                for (int mi = 0; mi < 2; mi++)
                    #pragma unroll
                    for (int ni = 0; ni < 8; ni++) {
                        const uint32_t* B = bh[ni >> 1];
                        const int o = (ni & 1) * 2;
                        mma16816(acc[mi][ni], al[mi], B[o], B[o + 1]);
                    }
            }
        }
    }

    // ---- fused epilogue (acc private; no barrier needed) ----
    const int tg = lane >> 2;        // 0..7
    const int tp = lane & 3;         // 0..3

    #pragma unroll
    for (int mi = 0; mi < 2; mi++) {
        #pragma unroll
        for (int h = 0; h < 2; h++) {
            const int r = arow0 + mi * 16 + tg + h * 8;
            #pragma unroll
            for (int ni = 0; ni < 8; ni++) {
                const int c = bc + ni * 8 + tp * 2;
                const size_t off = (size_t)r * NN + c;
                float v0 = acc[mi][ni][h * 2 + 0];
                float v1 = acc[mi][ni][h * 2 + 1];
                if (mode == 0) {
                    float2 bv = *(const float2*)&bias[c];
                    *(float2*)&Pout[off] = make_float2(v0 + bv.x, v1 + bv.y);
                } else {
                    float2 pv = *(const float2*)&P[off];
                    __nv_bfloat162 shp = *(const __nv_bfloat162*)(Ahi + off);
                    __nv_bfloat162 slp = *(const __nv_bfloat162*)(Alo + off);
                    float s0 = __bfloat162float(shp.x) + __bfloat162float(slp.x);
                    float s1 = __bfloat162float(shp.y) + __bfloat162float(slp.y);
                    float f0 = tanhf(pv.x + v0);
                    float f1 = tanhf(pv.y + v1);
                    float ns0 = s0 + 0.1f * (f0 - s0);
                    float ns1 = s1 + 0.1f * (f1 - s1);
                    __nv_bfloat16 h0 = __float2bfloat16(ns0);
                    __nv_bfloat16 h1 = __float2bfloat16(ns1);
                    __nv_bfloat162 nh, nl;
                    nh.x = h0; nh.y = h1;
                    nl.x = __float2bfloat16(ns0 - __bfloat162float(h0));
                    nl.y = __float2bfloat16(ns1 - __bfloat162float(h1));
                    *(__nv_bfloat162*)(NShi + off) = nh;
                    *(__nv_bfloat162*)(NSlo + off) = nl;
                    if (OutF)  *(float2*)&OutF[off]  = make_float2(ns0, ns1);
                    if (OutF2) *(float2*)&OutF2[off] = make_float2(ns0, ns1);
                }
            }
        }
    }
}

// ---- prep: split fp32 -> bf16 hi/lo for inputs and state ----
__global__ void split_kernel(const float* __restrict__ in, const float* __restrict__ st,
                             __nv_bfloat16* __restrict__ ih, __nv_bfloat16* __restrict__ il,
                             __nv_bfloat16* __restrict__ sh, __nv_bfloat16* __restrict__ sl)
{
    int t = blockIdx.x * blockDim.x + threadIdx.x;
    size_t i = (size_t)t * 4;
    if (i >= (size_t)BB * KK) return;
    float4 vi = *(const float4*)&in[i];
    float4 vs = *(const float4*)&st[i];
    const float* pi = (const float*)&vi;
    const float* ps = (const float*)&vs;
    __nv_bfloat16 a[4], b[4], c[4], d[4];
    #pragma unroll
    for (int j = 0; j < 4; j++) {
        __nv_bfloat16 h = __float2bfloat16(pi[j]);
        a[j] = h; b[j] = __float2bfloat16(pi[j] - __bfloat162float(h));
        __nv_bfloat16 h2 = __float2bfloat16(ps[j]);
        c[j] = h2; d[j] = __float2bfloat16(ps[j] - __bfloat162float(h2));
    }
    *(uint2*)(ih + i) = *(uint2*)a;
    *(uint2*)(il + i) = *(uint2*)b;
    *(uint2*)(sh + i) = *(uint2*)c;
    *(uint2*)(sl + i) = *(uint2*)d;
}

// ---- prep: transpose + split W -> Wt[n][k] hi/lo ----
__global__ void wprep_kernel(const float* __restrict__ W,
                             __nv_bfloat16* __restrict__ WtInHi, __nv_bfloat16* __restrict__ WtInLo,
                             __nv_bfloat16* __restrict__ WtRecHi, __nv_bfloat16* __restrict__ WtRecLo)
{
    int t = blockIdx.x * blockDim.x + threadIdx.x;
    if (t >= NN * KK) return;
    int k = t / NN, n = t % NN;
    int h = blockIdx.y;
    float v = W[(size_t)(k + h * KK) * NN + n];
    __nv_bfloat16 hi = __float2bfloat16(v);
    __nv_bfloat16 lo = __float2bfloat16(v - __bfloat162float(hi));
    size_t o = (size_t)n * KK + k;
    if (h == 0) { WtInHi[o] = hi; WtInLo[o] = lo; }
    else        { WtRecHi[o] = hi; WtRecLo[o] = lo; }
}

extern "C" void kernel_launch(void* const* d_in, const int* in_sizes, int n_in,
                              void* d_out, int out_size)
{
    const float* inputs = (const float*)d_in[0];
    const float* state  = (const float*)d_in[1];
    const float* W      = (const float*)d_in[2];
    const float* bias   = (const float*)d_in[3];
    float* out = (float*)d_out;
    float* out2 = (out_size >= 2 * BB * NN) ? (out + (size_t)BB * NN) : nullptr;

    __nv_bfloat16 *ih, *il, *sh0, *sl0, *sh1, *sl1, *wih, *wil, *wrh, *wrl;
    float* P;
    cudaGetSymbolAddress((void**)&ih,  g_in_hi);
    cudaGetSymbolAddress((void**)&il,  g_in_lo);
    cudaGetSymbolAddress((void**)&sh0, g_s_hi);  sh1 = sh0 + (size_t)BB * NN;
    cudaGetSymbolAddress((void**)&sl0, g_s_lo);  sl1 = sl0 + (size_t)BB * NN;
    cudaGetSymbolAddress((void**)&P,   g_P);
    cudaGetSymbolAddress((void**)&wih, g_WtIn_hi);
    cudaGetSymbolAddress((void**)&wil, g_WtIn_lo);
    cudaGetSymbolAddress((void**)&wrh, g_WtRec_hi);
    cudaGetSymbolAddress((void**)&wrl, g_WtRec_lo);

    cudaFuncSetAttribute(ctrnn_hmma, cudaFuncAttributeMaxDynamicSharedMemorySize, DSMEM);

    split_kernel<<<(BB * KK / 4 + 255) / 256, 256>>>(inputs, state, ih, il, sh0, sl0);
    wprep_kernel<<<dim3((NN * KK + 255) / 256, 2), 256>>>(W, wih, wil, wrh, wrl);

    dim3 grid(NN / TN, BB / TM);   // (8, 32) = 256 CTAs, 1/SM

    ctrnn_hmma<<<grid, 256, DSMEM>>>(ih, il, wih, wil, nullptr, bias, P,
                                     nullptr, nullptr, nullptr, nullptr, 0);
    ctrnn_hmma<<<grid, 256, DSMEM>>>(sh0, sl0, wrh, wrl, P, nullptr, nullptr,
                                     sh1, sl1, nullptr, nullptr, 1);
    ctrnn_hmma<<<grid, 256, DSMEM>>>(sh1, sl1, wrh, wrl, P, nullptr, nullptr,
                                     sh0, sl0, nullptr, nullptr, 1);
    ctrnn_hmma<<<grid, 256, DSMEM>>>(sh0, sl0, wrh, wrl, P, nullptr, nullptr,
                                     sh1, sl1, nullptr, nullptr, 1);
    ctrnn_hmma<<<grid, 256, DSMEM>>>(sh1, sl1, wrh, wrl, P, nullptr, nullptr,
                                     sh0, sl0, nullptr, nullptr, 1);
    ctrnn_hmma<<<grid, 256, DSMEM>>>(sh0, sl0, wrh, wrl, P, nullptr, nullptr,
                                     sh1, sl1, nullptr, nullptr, 1);
    ctrnn_hmma<<<grid, 256, DSMEM>>>(sh1, sl1, wrh, wrl, P, nullptr, nullptr,
                                     sh0, sl0, out, out2, 1);
}

// round 10
// speedup vs baseline: 2.2910x; 2.2910x over previous
#include <cuda_runtime.h>
#include <cuda_fp16.h>
#include <math.h>
#include <stdint.h>

// CTRNN B=8192, N=512, K=512, 6 unfolds + 1 precompute GEMM.
// R8/R9/R10: SINGLE-PASS fp16 HMMA (mma.sync.m16n8k16.f32.f16.f16.f32).
//   State is carried in fp32 (exact Euler update); only the GEMM operand is
//   an fp16 shadow. GEMM error ~2^-11 enters through tanh args only, damped
//   by dt=0.1 per unfold -> predicted rel_err ~1e-4.
//   P = inputs @ W_in + bias           (mode 0)
//   s' = s + 0.1*(tanh(P + s@W_rec)-s) (mode 1, x6)
// Geometry: CTA 128x128, warp 64x32, 2 CTAs/SM, 3-stage cp.async ring,
// K-chunk 64 (128B rows, XOR swizzle).

#define BB 8192
#define NN 512
#define KK 512

// ---- scratch (device globals; no allocs allowed) ----
__device__ __half g_A16[BB * KK];        // fp16(inputs)
__device__ __half g_S16[2][BB * NN];     // fp16 state operand (ping-pong)
__device__ float  g_S32[2][BB * NN];     // fp32 state (ping-pong)
__device__ float  g_P[BB * NN];
__device__ __half g_WtIn16[NN * KK];     // Wt[n][k] = W[k][n]
__device__ __half g_WtRec16[NN * KK];    // Wt[n][k] = W[k+512][n]

// ---- helpers ----
__device__ __forceinline__ uint32_t smem_u32(const void* p) {
    uint32_t a;
    asm("{ .reg .u64 t; cvta.to.shared.u64 t, %1; cvt.u32.u64 %0, t; }" : "=r"(a) : "l"(p));
    return a;
}
__device__ __forceinline__ void cp_async16(uint32_t dst, const void* src) {
    asm volatile("cp.async.cg.shared.global [%0], [%1], 16;" :: "r"(dst), "l"(src));
}
#define CP_COMMIT() asm volatile("cp.async.commit_group;" ::: "memory")
#define CP_WAIT1()  asm volatile("cp.async.wait_group 1;" ::: "memory")
#define CP_WAIT0()  asm volatile("cp.async.wait_group 0;" ::: "memory")

__device__ __forceinline__ void ldm4(uint32_t* r, uint32_t addr) {
    asm volatile("ldmatrix.sync.aligned.m8n8.x4.shared.b16 {%0,%1,%2,%3}, [%4];"
                 : "=r"(r[0]), "=r"(r[1]), "=r"(r[2]), "=r"(r[3]) : "r"(addr));
}
__device__ __forceinline__ void mma16816(float* d, const uint32_t* a, uint32_t b0, uint32_t b1) {
    asm volatile(
        "mma.sync.aligned.m16n8k16.row.col.f32.f16.f16.f32 "
        "{%0,%1,%2,%3}, {%4,%5,%6,%7}, {%8,%9}, {%0,%1,%2,%3};"
        : "+f"(d[0]), "+f"(d[1]), "+f"(d[2]), "+f"(d[3])
        : "r"(a[0]), "r"(a[1]), "r"(a[2]), "r"(a[3]), "r"(b0), "r"(b1));
}

// ---- geometry ----
#define TM 128
#define TN 128
#define TKC 64                 // K-chunk (fp16) = 128B rows
#define NCHUNK (KK / TKC)      // 8
#define NSTAGE 3
// 128B rows, SW128-ish swizzle: quad' = quad ^ (row & 7)
#define TILE_SZ (128 * 128)    // 16384 bytes (A or B tile)
#define BUF_B (2 * TILE_SZ)    // 32768 (A then B)
#define DSMEM (NSTAGE * BUF_B) // 98304

// fill a 128-row x 64-fp16 tile (128B swizzled rows) from [row0..][kc..kc+64)
__device__ __forceinline__ void fill_tile(uint32_t sbase, const __half* g,
                                          int row0, int kc, int tid) {
    #pragma unroll
    for (int c = tid; c < 1024; c += 256) {      // 1024 16B chunks
        int r = c >> 3, q = c & 7;
        uint32_t dst = sbase + (uint32_t)(r * 128 + ((q ^ (r & 7)) * 16));
        cp_async16(dst, g + (size_t)(row0 + r) * 512 + kc + q * 8);
    }
}

__global__ __launch_bounds__(256, 2)
void ctrnn_hmma(const __half* __restrict__ A16,     // GEMM operand [8192,512] fp16
                const __half* __restrict__ Wt16,    // Wt [N][K] fp16
                const float* __restrict__ P,        // mode1 in
                const float* __restrict__ S32in,    // mode1 in (fp32 state)
                const float* __restrict__ bias,     // mode0 in
                float* __restrict__ Pout,           // mode0 out
                __half* __restrict__ S16out,        // mode1 out (fp16 shadow)
                float* __restrict__ S32out,         // mode1 out (fp32 state)
                float* __restrict__ S32out2,        // optional dup
                int mode)
{
    extern __shared__ char dsm_raw[];
    const uint32_t dsm = smem_u32(dsm_raw);

    const int tid = threadIdx.x;
    const int w = tid >> 5;
    const int lane = tid & 31;
    const int warpM = w >> 2;        // 0..1 (64 rows each)
    const int warpN = w & 3;         // 0..3 (32 cols each)
    const int br = blockIdx.y * TM;
    const int bc = blockIdx.x * TN;

    float acc[4][4][4];
    #pragma unroll
    for (int mi = 0; mi < 4; mi++)
        #pragma unroll
        for (int ni = 0; ni < 4; ni++)
            #pragma unroll
            for (int q = 0; q < 4; q++) acc[mi][ni][q] = 0.0f;

    // per-lane swizzled ldmatrix base offsets (k16 group g => XOR g*32)
    uint32_t abase[4], bbase[2];
    {
        const int arl = lane & 15, aq = lane >> 4;
        #pragma unroll
        for (int mi = 0; mi < 4; mi++) {
            int row = warpM * 64 + mi * 16 + arl;
            abase[mi] = (uint32_t)(row * 128 + ((aq ^ (row & 7)) * 16));
        }
        const int brl = (lane >> 4) * 8 + (lane & 7), bq = (lane >> 3) & 1;
        #pragma unroll
        for (int p = 0; p < 2; p++) {
            int row = warpN * 32 + p * 16 + brl;
            bbase[p] = (uint32_t)(row * 128 + ((bq ^ (row & 7)) * 16));
        }
    }

    // prologue: fill stages 0,1 (chunks 0,1)
    #pragma unroll
    for (int s = 0; s < 2; s++) {
        uint32_t sb = dsm + s * BUF_B;
        fill_tile(sb,           A16,  br, s * TKC, tid);
        fill_tile(sb + TILE_SZ, Wt16, bc, s * TKC, tid);
        CP_COMMIT();
    }

    int stage = 0, fstage = 2;
    for (int i = 0; i < NCHUNK; i++) {
        if (i == NCHUNK - 1) { CP_WAIT0(); } else { CP_WAIT1(); }
        __syncthreads();     // also guards reuse of stage fstage
        if (i + 2 < NCHUNK) {
            uint32_t nb = dsm + fstage * BUF_B;
            fill_tile(nb,           A16,  br, (i + 2) * TKC, tid);
            fill_tile(nb + TILE_SZ, Wt16, bc, (i + 2) * TKC, tid);
            CP_COMMIT();
        }

        const uint32_t sb = dsm + stage * BUF_B;
        #pragma unroll
        for (int g = 0; g < 4; g++) {
            const uint32_t kx = (uint32_t)(g * 32);
            uint32_t a[4][4], b[2][4];
            #pragma unroll
            for (int mi = 0; mi < 4; mi++)
                ldm4(a[mi], (sb + abase[mi]) ^ kx);
            #pragma unroll
            for (int p = 0; p < 2; p++)
                ldm4(b[p], (sb + TILE_SZ + bbase[p]) ^ kx);
            #pragma unroll
            for (int mi = 0; mi < 4; mi++)
                #pragma unroll
                for (int ni = 0; ni < 4; ni++) {
                    const uint32_t* B = b[ni >> 1];
                    const int o = (ni & 1) * 2;
                    mma16816(acc[mi][ni], a[mi], B[o], B[o + 1]);
                }
        }
        stage = (stage + 1 == NSTAGE) ? 0 : stage + 1;
        fstage = (fstage + 1 == NSTAGE) ? 0 : fstage + 1;
    }

    // ---- fused epilogue ----
    const int tg = lane >> 2;        // 0..7
    const int tp = lane & 3;         // 0..3
    const int row0 = br + warpM * 64;
    const int col0 = bc + warpN * 32;

    #pragma unroll
    for (int mi = 0; mi < 4; mi++) {
        #pragma unroll
        for (int h = 0; h < 2; h++) {
            const int r = row0 + mi * 16 + tg + h * 8;
            #pragma unroll
            for (int ni = 0; ni < 4; ni++) {
                const int c = col0 + ni * 8 + tp * 2;
                const size_t off = (size_t)r * NN + c;
                float v0 = acc[mi][ni][h * 2 + 0];
                float v1 = acc[mi][ni][h * 2 + 1];
                if (mode == 0) {
                    float2 bv = *(const float2*)&bias[c];
                    *(float2*)&Pout[off] = make_float2(v0 + bv.x, v1 + bv.y);
                } else {
                    float2 pv = *(const float2*)&P[off];
                    float2 sv = *(const float2*)&S32in[off];
                    float f0 = tanhf(pv.x + v0);
                    float f1 = tanhf(pv.y + v1);
                    float ns0 = sv.x + 0.1f * (f0 - sv.x);
                    float ns1 = sv.y + 0.1f * (f1 - sv.y);
                    *(float2*)&S32out[off] = make_float2(ns0, ns1);
                    __half2 hp;
                    hp.x = __float2half(ns0);
                    hp.y = __float2half(ns1);
                    *(__half2*)(S16out + off) = hp;
                    if (S32out2) *(float2*)&S32out2[off] = make_float2(ns0, ns1);
                }
            }
        }
    }
}

// ---- prep: fp32 -> fp16 for inputs and state ----
#define SPLIT_VECS (BB * KK / 4)

__global__ void split_kernel(const float* __restrict__ in, const float* __restrict__ st,
                             __half* __restrict__ a16, __half* __restrict__ s16)
{
    int t = blockIdx.x * blockDim.x + threadIdx.x;
    if (t >= SPLIT_VECS) return;
    size_t i = (size_t)t * 4;
    float4 vi = *(const float4*)&in[i];
    float4 vs = *(const float4*)&st[i];
    __half2 a0, a1, s0, s1;
    a0.x = __float2half(vi.x); a0.y = __float2half(vi.y);
    a1.x = __float2half(vi.z); a1.y = __float2half(vi.w);
    s0.x = __float2half(vs.x); s0.y = __float2half(vs.y);
    s1.x = __float2half(vs.z); s1.y = __float2half(vs.w);
    *(__half2*)(a16 + i)     = a0;
    *(__half2*)(a16 + i + 2) = a1;
    *(__half2*)(s16 + i)     = s0;
    *(__half2*)(s16 + i + 2) = s1;
}

// ---- prep: transpose W -> Wt[n][k] fp16 (both halves) ----
__global__ void wprep_kernel(const float* __restrict__ W,
                             __half* __restrict__ WtIn, __half* __restrict__ WtRec)
{
    int t = blockIdx.x * blockDim.x + threadIdx.x;
    if (t >= NN * KK) return;
    int k = t / NN, n = t % NN;
    int h = blockIdx.y;
    float v = W[(size_t)(k + h * KK) * NN + n];
    size_t o = (size_t)n * KK + k;
    if (h == 0) WtIn[o]  = __float2half(v);
    else        WtRec[o] = __float2half(v);
}

extern "C" void kernel_launch(void* const* d_in, const int* in_sizes, int n_in,
                              void* d_out, int out_size)
{
    const float* inputs = (const float*)d_in[0];
    const float* state  = (const float*)d_in[1];
    const float* W      = (const float*)d_in[2];
    const float* bias   = (const float*)d_in[3];
    float* out = (float*)d_out;
    float* out2 = (out_size >= 2 * BB * NN) ? (out + (size_t)BB * NN) : nullptr;

    __half *a16, *s16_0, *s16_1, *wtin, *wtrec;
    float *s32_0, *s32_1, *P;
    cudaGetSymbolAddress((void**)&a16,   g_A16);
    cudaGetSymbolAddress((void**)&s16_0, g_S16);  s16_1 = s16_0 + (size_t)BB * NN;
    cudaGetSymbolAddress((void**)&s32_0, g_S32);  s32_1 = s32_0 + (size_t)BB * NN;
    cudaGetSymbolAddress((void**)&P,     g_P);
    cudaGetSymbolAddress((void**)&wtin,  g_WtIn16);
    cudaGetSymbolAddress((void**)&wtrec, g_WtRec16);

    cudaFuncSetAttribute(ctrnn_hmma, cudaFuncAttributeMaxDynamicSharedMemorySize, DSMEM);

    split_kernel<<<(SPLIT_VECS + 255) / 256, 256>>>(inputs, state, a16, s16_0);
    wprep_kernel<<<dim3((NN * KK + 255) / 256, 2), 256>>>(W, wtin, wtrec);

    dim3 grid(NN / TN, BB / TM);   // (4, 64) = 256 CTAs

    // P = inputs @ W_in + bias
    ctrnn_hmma<<<grid, 256, DSMEM>>>(a16, wtin, nullptr, nullptr, bias, P,
                                     nullptr, nullptr, nullptr, 0);
    // 6 unfolds: fp16 operand ping-pong, fp32 state ping-pong
    ctrnn_hmma<<<grid, 256, DSMEM>>>(s16_0, wtrec, P, state, nullptr, nullptr,
                                     s16_1, s32_0, nullptr, 1);
    ctrnn_hmma<<<grid, 256, DSMEM>>>(s16_1, wtrec, P, s32_0, nullptr, nullptr,
                                     s16_0, s32_1, nullptr, 1);
    ctrnn_hmma<<<grid, 256, DSMEM>>>(s16_0, wtrec, P, s32_1, nullptr, nullptr,
                                     s16_1, s32_0, nullptr, 1);
    ctrnn_hmma<<<grid, 256, DSMEM>>>(s16_1, wtrec, P, s32_0, nullptr, nullptr,
                                     s16_0, s32_1, nullptr, 1);
    ctrnn_hmma<<<grid, 256, DSMEM>>>(s16_0, wtrec, P, s32_1, nullptr, nullptr,
                                     s16_1, s32_0, nullptr, 1);
    ctrnn_hmma<<<grid, 256, DSMEM>>>(s16_1, wtrec, P, s32_0, nullptr, nullptr,
                                     s16_0, out, out2, 1);
}